// round 15
// baseline (speedup 1.0000x reference)
#include <cuda_runtime.h>
#include <math.h>
#include <stdint.h>

#define NE 64
#define NH 512
#define NF 2048
#define NT 2048

// scratch: h = gelu(x @ w1^T) (16 MB)
__device__ float g_h[(size_t)NT * NF];

// ---------------- helpers ----------------
__device__ __forceinline__ uint32_t smem_u32(const void* p) {
    return (uint32_t)__cvta_generic_to_shared(p);
}
__device__ __forceinline__ uint32_t sw128(uint32_t off) { return off ^ ((off >> 3) & 0x70); }

__device__ __forceinline__ void ldm_x4(uint32_t* r, uint32_t a) {
    asm volatile("ldmatrix.sync.aligned.m8n8.x4.shared.b16 {%0,%1,%2,%3}, [%4];"
                 : "=r"(r[0]), "=r"(r[1]), "=r"(r[2]), "=r"(r[3]) : "r"(a));
}
__device__ __forceinline__ void ldm_x4_t(uint32_t* r, uint32_t a) {
    asm volatile("ldmatrix.sync.aligned.m8n8.x4.trans.shared.b16 {%0,%1,%2,%3}, [%4];"
                 : "=r"(r[0]), "=r"(r[1]), "=r"(r[2]), "=r"(r[3]) : "r"(a));
}
__device__ __forceinline__ void mma_bf16(float* c, const uint32_t* a, const uint32_t* b) {
    asm volatile(
        "mma.sync.aligned.m16n8k16.row.col.f32.bf16.bf16.f32 "
        "{%0,%1,%2,%3}, {%4,%5,%6,%7}, {%8,%9}, {%0,%1,%2,%3};"
        : "+f"(c[0]), "+f"(c[1]), "+f"(c[2]), "+f"(c[3])
        : "r"(a[0]), "r"(a[1]), "r"(a[2]), "r"(a[3]), "r"(b[0]), "r"(b[1]));
}
__device__ __forceinline__ float gelu_exact(float v) {
    return 0.5f * v * (1.0f + erff(v * 0.7071067811865476f));
}
__device__ __forceinline__ void split4(const float4 t, uint64_t& hi, uint64_t& lo) {
    uint32_t h01, h23, l01, l23;
    asm("cvt.rn.bf16x2.f32 %0, %1, %2;" : "=r"(h01) : "f"(t.y), "f"(t.x));
    asm("cvt.rn.bf16x2.f32 %0, %1, %2;" : "=r"(h23) : "f"(t.w), "f"(t.z));
    const float rx = t.x - __uint_as_float(h01 << 16);
    const float ry = t.y - __uint_as_float(h01 & 0xffff0000u);
    const float rz = t.z - __uint_as_float(h23 << 16);
    const float rw = t.w - __uint_as_float(h23 & 0xffff0000u);
    asm("cvt.rn.bf16x2.f32 %0, %1, %2;" : "=r"(l01) : "f"(ry), "f"(rx));
    asm("cvt.rn.bf16x2.f32 %0, %1, %2;" : "=r"(l23) : "f"(rw), "f"(rz));
    hi = ((uint64_t)h23 << 32) | h01;
    lo = ((uint64_t)l23 << 32) | l01;
}

__device__ __forceinline__ void expert_range(const int* __restrict__ counts, int e,
                                             int& base, int& cnt) {
    int b = 0, c = 0;
    #pragma unroll
    for (int j = 0; j < NE; ++j) {
        const int v = __ldg(counts + j);
        if (j < e) b += v;
        if (j == e) c = v;
    }
    base = b; cnt = c;
}

// ---------------- f32 tile load (regs) + split-convert store (smem) ----------
// Tile: R rows x 64 f32 cols. 128 threads: 16 threads/row (float4), 8 rows/pass.
template<int R>
__device__ __forceinline__ void load_f32(float4* v, const float* __restrict__ src,
                                         int stride, int valid, int tid) {
    const int row0 = tid >> 4, c4 = (tid & 15) * 4;
    #pragma unroll
    for (int p = 0; p < R / 8; ++p) {
        const int row = p * 8 + row0;
        v[p] = (row < valid) ? *(const float4*)(src + (size_t)row * stride + c4)
                             : make_float4(0.f, 0.f, 0.f, 0.f);
    }
}
template<int R>
__device__ __forceinline__ void store_split(const float4* v, char* hi, char* lo, int tid) {
    const int row0 = tid >> 4, l15 = tid & 15;
    #pragma unroll
    for (int p = 0; p < R / 8; ++p) {
        const int row = p * 8 + row0;
        uint64_t h, l;
        split4(v[p], h, l);
        const uint32_t off = sw128((uint32_t)(row * 128 + l15 * 8));
        *(uint64_t*)(hi + off) = h;
        *(uint64_t*)(lo + off) = l;
    }
}

// ---- gemm2 B half (32 k-rows x 128 f32 of n), h in {0,1}; 128 threads -------
// stored as two n64-subtiles (8KB each): sub = n>>6 (R6-proven image)
__device__ __forceinline__ void ldgB2w(float4* v, const float* __restrict__ src,
                                       int h, int tid) {
    const int row0 = tid >> 5, c4 = (tid & 31) * 4;
    #pragma unroll
    for (int p = 0; p < 8; ++p)
        v[p] = *(const float4*)(src + (size_t)(h * 32 + p * 4 + row0) * NH + c4);
}
__device__ __forceinline__ void stsB2w(const float4* v, char* hi, char* lo, int h, int tid) {
    const int row0 = tid >> 5;
    const int n4 = (tid & 31) * 4;
    const int sub = n4 >> 6;
    const int nn2 = (n4 & 63) * 2;
    #pragma unroll
    for (int p = 0; p < 8; ++p) {
        const int krow = h * 32 + p * 4 + row0;
        uint64_t hq, lq;
        split4(v[p], hq, lq);
        const uint32_t off = sub * 8192 + sw128((uint32_t)(krow * 128 + nn2));
        *(uint64_t*)(hi + off) = hq;
        *(uint64_t*)(lo + off) = lq;
    }
}

// gemm1 stage: [Ahi 4K][Alo 4K][Bhi 16K][Blo 16K] = 40K; x2 = 80K per CTA
#define BSZ1 (40 * 1024)
// gemm2 stage: [Ahi 4K][Alo 4K][Bhi 16K][Blo 16K] = 40K; x2 = 80K per CTA
#define BSZ2 (40 * 1024)

// ---------------- GEMM1 + GELU: h = gelu(x @ w1[e]^T) ------------------------
// CTA: (f-slab 128, expert). M=32, K-tiles of 64 (8). 4 warps = 1m x 4n.
// Warp tile 32m x 32n — A fragments reused across 2 n-frag groups. (R14 verbatim)
__global__ void __launch_bounds__(128, 2) gemm1_tc(const float* __restrict__ x,
                                                   const float* __restrict__ w1,
                                                   const int* __restrict__ counts) {
    extern __shared__ char sm[];
    const int e  = blockIdx.y;
    const int f0 = blockIdx.x * 128;
    int base, cnt;
    expert_range(counts, e, base, cnt);
    const int tid = threadIdx.x, warp = tid >> 5, lane = tid & 31;
    const int wn = warp;   // 0..3
    const float* w1e = w1 + (size_t)e * NF * NH + (size_t)f0 * NH;

    const int arow = lane & 15, acol = lane & 16;        // A (plain)
    const int brow = (lane & 7) + ((lane >> 1) & 8);     // B (plain, [n][k])
    const int bcol = (lane & 8) * 2;

    for (int mm = 0; mm < cnt; mm += 32) {
        const int rem = cnt - mm;
        const int va = rem < 32 ? rem : 32;
        const float* xa = x + (size_t)(base + mm) * NH;

        float c[2][4][4];
        #pragma unroll
        for (int i = 0; i < 2; ++i)
            #pragma unroll
            for (int j = 0; j < 4; ++j)
                #pragma unroll
                for (int q = 0; q < 4; ++q) c[i][j][q] = 0.f;

        {
            float4 rA[4], rB[16];
            load_f32<32>(rA, xa, NH, va, tid);
            load_f32<128>(rB, w1e, NH, 128, tid);
            store_split<32>(rA, sm, sm + 4096, tid);
            store_split<128>(rB, sm + 8192, sm + 24576, tid);
        }

        for (int kt = 0; kt < 8; ++kt) {
            __syncthreads();
            char* bb = sm + (kt & 1) * BSZ1;
            char* nb = sm + ((kt + 1) & 1) * BSZ1;
            const bool pf = (kt + 1) < 8;
            float4 rA[4], rB[16];
            if (pf) {
                const int k0 = (kt + 1) * 64;
                load_f32<32>(rA, xa + k0, NH, va, tid);
                load_f32<128>(rB, w1e + k0, NH, 128, tid);
            }
            const uint32_t uAh = smem_u32(bb), uAl = uAh + 4096;
            const uint32_t uBh = uAh + 8192, uBl = uAh + 24576;
            #pragma unroll
            for (int kk = 0; kk < 4; ++kk) {
                uint32_t ah[2][4], al[2][4];
                #pragma unroll
                for (int mi = 0; mi < 2; ++mi) {
                    const uint32_t off =
                        sw128((uint32_t)((mi * 16 + arow) * 128 + kk * 32 + acol));
                    ldm_x4(ah[mi], uAh + off);
                    ldm_x4(al[mi], uAl + off);
                }
                #pragma unroll
                for (int nbk = 0; nbk < 2; ++nbk) {
                    uint32_t bh[4], bl[4];
                    const uint32_t off =
                        sw128((uint32_t)((wn * 32 + nbk * 16 + brow) * 128 + kk * 32 + bcol));
                    ldm_x4(bh, uBh + off);
                    ldm_x4(bl, uBl + off);
                    #pragma unroll
                    for (int mi = 0; mi < 2; ++mi)
                        #pragma unroll
                        for (int j = 0; j < 2; ++j) {
                            float* cc = c[mi][nbk * 2 + j];
                            mma_bf16(cc, ah[mi], &bh[j * 2]);
                            mma_bf16(cc, ah[mi], &bl[j * 2]);
                            mma_bf16(cc, al[mi], &bh[j * 2]);
                        }
                }
            }
            if (pf) {
                store_split<32>(rA, nb, nb + 4096, tid);
                store_split<128>(rB, nb + 8192, nb + 24576, tid);
            }
        }

        const int r0 = lane >> 2, cp = (lane & 3) * 2;
        #pragma unroll
        for (int mi = 0; mi < 2; ++mi)
            #pragma unroll
            for (int nj = 0; nj < 4; ++nj) {
                const int rloc = mi * 16 + r0;
                const int ncol = f0 + wn * 32 + (nj >> 1) * 16 + (nj & 1) * 8 + cp;
                if (rloc < va) {
                    float2 o = make_float2(gelu_exact(c[mi][nj][0]), gelu_exact(c[mi][nj][1]));
                    *(float2*)&g_h[(size_t)(base + mm + rloc) * NF + ncol] = o;
                }
                if (rloc + 8 < va) {
                    float2 o = make_float2(gelu_exact(c[mi][nj][2]), gelu_exact(c[mi][nj][3]));
                    *(float2*)&g_h[(size_t)(base + mm + rloc + 8) * NF + ncol] = o;
                }
            }
        __syncthreads();
    }
}

// ---------------- zero out ----------------
__global__ void zero_out(float4* __restrict__ out) {
    out[blockIdx.x * 256 + threadIdx.x] = make_float4(0.f, 0.f, 0.f, 0.f);
}

// ---------------- GEMM2: out += h @ w2[e]  (k-split x2, atomic epilogue) -----
// CTA: (n-slab 128, expert, k-half). M=32, K-tiles of 64 (16 per half).
// 4 warps = 1m x 4n; warp tile 32m x 32n. R6's N128 trans-B mapping.
__global__ void __launch_bounds__(128, 2) gemm2_tc(const float* __restrict__ w2,
                                                   float* __restrict__ out,
                                                   const int* __restrict__ counts) {
    extern __shared__ char sm[];
    const int e  = blockIdx.y;
    const int n0 = blockIdx.x * 128;
    const int kb = blockIdx.z * 1024;
    int base, cnt;
    expert_range(counts, e, base, cnt);
    const int tid = threadIdx.x, warp = tid >> 5, lane = tid & 31;
    const int wn = warp;   // 0..3
    const float* w2e = w2 + (size_t)e * NF * NH + n0;

    const int arow = lane & 15, acol = lane & 16;   // A (plain)
    const int tbrow = lane & 15, tbcol = lane & 16; // B (trans, [k][n])

    for (int mm = 0; mm < cnt; mm += 32) {
        const int rem = cnt - mm;
        const int va = rem < 32 ? rem : 32;
        const float* ha = g_h + (size_t)(base + mm) * NF + kb;

        float c[2][4][4];
        #pragma unroll
        for (int i = 0; i < 2; ++i)
            #pragma unroll
            for (int j = 0; j < 4; ++j)
                #pragma unroll
                for (int q = 0; q < 4; ++q) c[i][j][q] = 0.f;

        {
            float4 rA[4], rB0[8], rB1[8];
            load_f32<32>(rA, ha, NF, va, tid);
            ldgB2w(rB0, w2e + (size_t)kb * NH, 0, tid);
            ldgB2w(rB1, w2e + (size_t)kb * NH, 1, tid);
            store_split<32>(rA, sm, sm + 4096, tid);
            stsB2w(rB0, sm + 8192, sm + 24576, 0, tid);
            stsB2w(rB1, sm + 8192, sm + 24576, 1, tid);
        }

        for (int kt = 0; kt < 16; ++kt) {
            __syncthreads();
            char* bb = sm + (kt & 1) * BSZ2;
            char* nb = sm + ((kt + 1) & 1) * BSZ2;
            const bool pf = (kt + 1) < 16;
            float4 rA[4], rB0[8], rB1[8];
            if (pf) {
                const int k0 = (kt + 1) * 64;
                load_f32<32>(rA, ha + k0, NF, va, tid);
                ldgB2w(rB0, w2e + (size_t)(kb + k0) * NH, 0, tid);
                ldgB2w(rB1, w2e + (size_t)(kb + k0) * NH, 1, tid);
            }
            const uint32_t uAh = smem_u32(bb), uAl = uAh + 4096;
            const uint32_t uBh = uAh + 8192, uBl = uAh + 24576;
            #pragma unroll
            for (int kk = 0; kk < 4; ++kk) {
                uint32_t ah[2][4], al[2][4];
                #pragma unroll
                for (int mi = 0; mi < 2; ++mi) {
                    const uint32_t off =
                        sw128((uint32_t)((mi * 16 + arow) * 128 + kk * 32 + acol));
                    ldm_x4(ah[mi], uAh + off);
                    ldm_x4(al[mi], uAl + off);
                }
                #pragma unroll
                for (int nbk = 0; nbk < 2; ++nbk) {
                    const int g = wn * 2 + nbk;
                    uint32_t bh[4], bl[4];
                    const uint32_t off = (uint32_t)((g >> 2) * 8192) +
                        sw128((uint32_t)((kk * 16 + tbrow) * 128 + (g & 3) * 32 + tbcol));
                    ldm_x4_t(bh, uBh + off);
                    ldm_x4_t(bl, uBl + off);
                    #pragma unroll
                    for (int mi = 0; mi < 2; ++mi)
                        #pragma unroll
                        for (int j = 0; j < 2; ++j) {
                            float* cc = c[mi][nbk * 2 + j];
                            mma_bf16(cc, ah[mi], &bh[j * 2]);
                            mma_bf16(cc, ah[mi], &bl[j * 2]);
                            mma_bf16(cc, al[mi], &bh[j * 2]);
                        }
                }
            }
            if (pf) {
                store_split<32>(rA, nb, nb + 4096, tid);
                stsB2w(rB0, nb + 8192, nb + 24576, 0, tid);
                stsB2w(rB1, nb + 8192, nb + 24576, 1, tid);
            }
        }

        // epilogue: atomic accumulate (exactly 2 contributions per element)
        const int r0 = lane >> 2, cp = (lane & 3) * 2;
        #pragma unroll
        for (int mi = 0; mi < 2; ++mi)
            #pragma unroll
            for (int nj = 0; nj < 4; ++nj) {
                const int g = wn * 2 + (nj >> 1);
                const int rloc = mi * 16 + r0;
                const int ncol = n0 + g * 16 + (nj & 1) * 8 + cp;
                if (rloc < va) {
                    float* p = &out[(size_t)(base + mm + rloc) * NH + ncol];
                    atomicAdd(p, c[mi][nj][0]);
                    atomicAdd(p + 1, c[mi][nj][1]);
                }
                if (rloc + 8 < va) {
                    float* p = &out[(size_t)(base + mm + rloc + 8) * NH + ncol];
                    atomicAdd(p, c[mi][nj][2]);
                    atomicAdd(p + 1, c[mi][nj][3]);
                }
            }
        __syncthreads();
    }
}

// ---------------------------------------------------------------------------
extern "C" void kernel_launch(void* const* d_in, const int* in_sizes, int n_in,
                              void* d_out, int out_size) {
    const float* x  = (const float*)d_in[0];
    const float* w1 = (const float*)d_in[1];
    const float* w2 = (const float*)d_in[2];
    const int* tokens_per_expert = (const int*)d_in[3];
    float* out = (float*)d_out;

    cudaFuncSetAttribute(gemm1_tc, cudaFuncAttributeMaxDynamicSharedMemorySize, 2 * BSZ1);
    cudaFuncSetAttribute(gemm2_tc, cudaFuncAttributeMaxDynamicSharedMemorySize, 2 * BSZ2);

    gemm1_tc<<<dim3(NF / 128, NE), 128, 2 * BSZ1>>>(x, w1, tokens_per_expert);
    zero_out<<<(NT * NH) / 1024, 256>>>((float4*)out);
    gemm2_tc<<<dim3(NH / 128, NE, 2), 128, 2 * BSZ2>>>(w2, out, tokens_per_expert);
}

// round 16
// speedup vs baseline: 1.0563x; 1.0563x over previous
#include <cuda_runtime.h>
#include <math.h>
#include <stdint.h>

#define NE 64
#define NH 512
#define NF 2048
#define NT 2048

// scratch: h = gelu(x @ w1^T) (16 MB)
__device__ float g_h[(size_t)NT * NF];

// ---------------- helpers ----------------
__device__ __forceinline__ uint32_t smem_u32(const void* p) {
    return (uint32_t)__cvta_generic_to_shared(p);
}
__device__ __forceinline__ uint32_t sw128(uint32_t off) { return off ^ ((off >> 3) & 0x70); }

__device__ __forceinline__ void ldm_x4(uint32_t* r, uint32_t a) {
    asm volatile("ldmatrix.sync.aligned.m8n8.x4.shared.b16 {%0,%1,%2,%3}, [%4];"
                 : "=r"(r[0]), "=r"(r[1]), "=r"(r[2]), "=r"(r[3]) : "r"(a));
}
__device__ __forceinline__ void ldm_x4_t(uint32_t* r, uint32_t a) {
    asm volatile("ldmatrix.sync.aligned.m8n8.x4.trans.shared.b16 {%0,%1,%2,%3}, [%4];"
                 : "=r"(r[0]), "=r"(r[1]), "=r"(r[2]), "=r"(r[3]) : "r"(a));
}
__device__ __forceinline__ void mma_bf16(float* c, const uint32_t* a, const uint32_t* b) {
    asm volatile(
        "mma.sync.aligned.m16n8k16.row.col.f32.bf16.bf16.f32 "
        "{%0,%1,%2,%3}, {%4,%5,%6,%7}, {%8,%9}, {%0,%1,%2,%3};"
        : "+f"(c[0]), "+f"(c[1]), "+f"(c[2]), "+f"(c[3])
        : "r"(a[0]), "r"(a[1]), "r"(a[2]), "r"(a[3]), "r"(b[0]), "r"(b[1]));
}
__device__ __forceinline__ float gelu_exact(float v) {
    return 0.5f * v * (1.0f + erff(v * 0.7071067811865476f));
}
__device__ __forceinline__ void split4(const float4 t, uint64_t& hi, uint64_t& lo) {
    uint32_t h01, h23, l01, l23;
    asm("cvt.rn.bf16x2.f32 %0, %1, %2;" : "=r"(h01) : "f"(t.y), "f"(t.x));
    asm("cvt.rn.bf16x2.f32 %0, %1, %2;" : "=r"(h23) : "f"(t.w), "f"(t.z));
    const float rx = t.x - __uint_as_float(h01 << 16);
    const float ry = t.y - __uint_as_float(h01 & 0xffff0000u);
    const float rz = t.z - __uint_as_float(h23 << 16);
    const float rw = t.w - __uint_as_float(h23 & 0xffff0000u);
    asm("cvt.rn.bf16x2.f32 %0, %1, %2;" : "=r"(l01) : "f"(ry), "f"(rx));
    asm("cvt.rn.bf16x2.f32 %0, %1, %2;" : "=r"(l23) : "f"(rw), "f"(rz));
    hi = ((uint64_t)h23 << 32) | h01;
    lo = ((uint64_t)l23 << 32) | l01;
}

__device__ __forceinline__ void expert_range(const int* __restrict__ counts, int e,
                                             int& base, int& cnt) {
    int b = 0, c = 0;
    #pragma unroll
    for (int j = 0; j < NE; ++j) {
        const int v = __ldg(counts + j);
        if (j < e) b += v;
        if (j == e) c = v;
    }
    base = b; cnt = c;
}

// ======== 128-thread tile helpers (gemm1, R14-proven) ========
// Tile: R rows x 64 f32 cols. 128 threads: 16 threads/row (float4), 8 rows/pass.
template<int R>
__device__ __forceinline__ void load_f32_g1(float4* v, const float* __restrict__ src,
                                            int stride, int valid, int tid) {
    const int row0 = tid >> 4, c4 = (tid & 15) * 4;
    #pragma unroll
    for (int p = 0; p < R / 8; ++p) {
        const int row = p * 8 + row0;
        v[p] = (row < valid) ? *(const float4*)(src + (size_t)row * stride + c4)
                             : make_float4(0.f, 0.f, 0.f, 0.f);
    }
}
template<int R>
__device__ __forceinline__ void store_split_g1(const float4* v, char* hi, char* lo, int tid) {
    const int row0 = tid >> 4, l15 = tid & 15;
    #pragma unroll
    for (int p = 0; p < R / 8; ++p) {
        const int row = p * 8 + row0;
        uint64_t h, l;
        split4(v[p], h, l);
        const uint32_t off = sw128((uint32_t)(row * 128 + l15 * 8));
        *(uint64_t*)(hi + off) = h;
        *(uint64_t*)(lo + off) = l;
    }
}

// ======== 256-thread tile helpers (gemm2, R8-proven) ========
// Tile: 64 rows x 64 f32 cols. 256 threads: 16 threads/row (float4), 16 rows/pass.
__device__ __forceinline__ void load_f32_g2(float4* v, const float* __restrict__ src,
                                            int stride, int valid, int tid) {
    const int row0 = tid >> 4, c4 = (tid & 15) * 4;
    #pragma unroll
    for (int p = 0; p < 4; ++p) {
        const int row = p * 16 + row0;
        v[p] = (row < valid) ? *(const float4*)(src + (size_t)row * stride + c4)
                             : make_float4(0.f, 0.f, 0.f, 0.f);
    }
}
__device__ __forceinline__ void store_split_g2(const float4* v, char* hi, char* lo, int tid) {
    const int row0 = tid >> 4, l15 = tid & 15;
    #pragma unroll
    for (int p = 0; p < 4; ++p) {
        const int row = p * 16 + row0;
        uint64_t h, l;
        split4(v[p], h, l);
        const uint32_t off = sw128((uint32_t)(row * 128 + l15 * 8));
        *(uint64_t*)(hi + off) = h;
        *(uint64_t*)(lo + off) = l;
    }
}

// gemm1 stage: [Ahi 4K][Alo 4K][Bhi 16K][Blo 16K] = 40K; x2 = 80K per CTA
#define BSZ1 (40 * 1024)
// gemm2 stage: [Ahi 8K][Alo 8K][Bhi 8K][Blo 8K] = 32K; x2 = 64K per CTA
#define BSZ2 (32 * 1024)

// ---------------- GEMM1 + GELU: h = gelu(x @ w1[e]^T) ------------------------
// CTA: (f-slab 128, expert). M=32, K-tiles of 64 (8). 4 warps = 1m x 4n.
// Warp tile 32m x 32n. (R14 verbatim — measured 94.9us)
__global__ void __launch_bounds__(128, 2) gemm1_tc(const float* __restrict__ x,
                                                   const float* __restrict__ w1,
                                                   const int* __restrict__ counts) {
    extern __shared__ char sm[];
    const int e  = blockIdx.y;
    const int f0 = blockIdx.x * 128;
    int base, cnt;
    expert_range(counts, e, base, cnt);
    const int tid = threadIdx.x, warp = tid >> 5, lane = tid & 31;
    const int wn = warp;   // 0..3
    const float* w1e = w1 + (size_t)e * NF * NH + (size_t)f0 * NH;

    const int arow = lane & 15, acol = lane & 16;        // A (plain)
    const int brow = (lane & 7) + ((lane >> 1) & 8);     // B (plain, [n][k])
    const int bcol = (lane & 8) * 2;

    for (int mm = 0; mm < cnt; mm += 32) {
        const int rem = cnt - mm;
        const int va = rem < 32 ? rem : 32;
        const float* xa = x + (size_t)(base + mm) * NH;

        float c[2][4][4];
        #pragma unroll
        for (int i = 0; i < 2; ++i)
            #pragma unroll
            for (int j = 0; j < 4; ++j)
                #pragma unroll
                for (int q = 0; q < 4; ++q) c[i][j][q] = 0.f;

        {
            float4 rA[4], rB[16];
            load_f32_g1<32>(rA, xa, NH, va, tid);
            load_f32_g1<128>(rB, w1e, NH, 128, tid);
            store_split_g1<32>(rA, sm, sm + 4096, tid);
            store_split_g1<128>(rB, sm + 8192, sm + 24576, tid);
        }

        for (int kt = 0; kt < 8; ++kt) {
            __syncthreads();
            char* bb = sm + (kt & 1) * BSZ1;
            char* nb = sm + ((kt + 1) & 1) * BSZ1;
            const bool pf = (kt + 1) < 8;
            float4 rA[4], rB[16];
            if (pf) {
                const int k0 = (kt + 1) * 64;
                load_f32_g1<32>(rA, xa + k0, NH, va, tid);
                load_f32_g1<128>(rB, w1e + k0, NH, 128, tid);
            }
            const uint32_t uAh = smem_u32(bb), uAl = uAh + 4096;
            const uint32_t uBh = uAh + 8192, uBl = uAh + 24576;
            #pragma unroll
            for (int kk = 0; kk < 4; ++kk) {
                uint32_t ah[2][4], al[2][4];
                #pragma unroll
                for (int mi = 0; mi < 2; ++mi) {
                    const uint32_t off =
                        sw128((uint32_t)((mi * 16 + arow) * 128 + kk * 32 + acol));
                    ldm_x4(ah[mi], uAh + off);
                    ldm_x4(al[mi], uAl + off);
                }
                #pragma unroll
                for (int nbk = 0; nbk < 2; ++nbk) {
                    uint32_t bh[4], bl[4];
                    const uint32_t off =
                        sw128((uint32_t)((wn * 32 + nbk * 16 + brow) * 128 + kk * 32 + bcol));
                    ldm_x4(bh, uBh + off);
                    ldm_x4(bl, uBl + off);
                    #pragma unroll
                    for (int mi = 0; mi < 2; ++mi)
                        #pragma unroll
                        for (int j = 0; j < 2; ++j) {
                            float* cc = c[mi][nbk * 2 + j];
                            mma_bf16(cc, ah[mi], &bh[j * 2]);
                            mma_bf16(cc, ah[mi], &bl[j * 2]);
                            mma_bf16(cc, al[mi], &bh[j * 2]);
                        }
                }
            }
            if (pf) {
                store_split_g1<32>(rA, nb, nb + 4096, tid);
                store_split_g1<128>(rB, nb + 8192, nb + 24576, tid);
            }
        }

        const int r0 = lane >> 2, cp = (lane & 3) * 2;
        #pragma unroll
        for (int mi = 0; mi < 2; ++mi)
            #pragma unroll
            for (int nj = 0; nj < 4; ++nj) {
                const int rloc = mi * 16 + r0;
                const int ncol = f0 + wn * 32 + (nj >> 1) * 16 + (nj & 1) * 8 + cp;
                if (rloc < va) {
                    float2 o = make_float2(gelu_exact(c[mi][nj][0]), gelu_exact(c[mi][nj][1]));
                    *(float2*)&g_h[(size_t)(base + mm + rloc) * NF + ncol] = o;
                }
                if (rloc + 8 < va) {
                    float2 o = make_float2(gelu_exact(c[mi][nj][2]), gelu_exact(c[mi][nj][3]));
                    *(float2*)&g_h[(size_t)(base + mm + rloc + 8) * NF + ncol] = o;
                }
            }
        __syncthreads();
    }
}

// ---------------- zero out ----------------
__global__ void zero_out(float4* __restrict__ out) {
    out[blockIdx.x * 256 + threadIdx.x] = make_float4(0.f, 0.f, 0.f, 0.f);
}

// ---------------- GEMM2: out += h @ w2[e]  (k-split x2, atomic epilogue) -----
// CTA: (n-slab 64, expert, k-half). M=64 padded, K-tiles of 64 (16 per half).
// 256 threads, 8 warps = 2m x 4n. (R8 verbatim — measured ~93.5us)
__global__ void __launch_bounds__(256, 2) gemm2_tc(const float* __restrict__ w2,
                                                   float* __restrict__ out,
                                                   const int* __restrict__ counts) {
    extern __shared__ char sm[];
    const int e  = blockIdx.y;
    const int n0 = blockIdx.x * 64;
    const int kb = blockIdx.z * 1024;
    int base, cnt;
    expert_range(counts, e, base, cnt);
    const int tid = threadIdx.x, warp = tid >> 5, lane = tid & 31;
    const int wm = warp >> 2, wn = warp & 3;
    const float* w2e = w2 + (size_t)e * NF * NH + n0;

    const int arow = lane & 15, acol = lane & 16;   // A (plain)
    const int tbrow = lane & 15, tbcol = lane & 16; // B (trans, [k][n])

    for (int mm = 0; mm < cnt; mm += 64) {
        const int rem = cnt - mm;
        const int va = rem < 64 ? rem : 64;
        const float* ha = g_h + (size_t)(base + mm) * NF + kb;

        float c[2][2][4];
        #pragma unroll
        for (int i = 0; i < 2; ++i)
            #pragma unroll
            for (int j = 0; j < 2; ++j)
                #pragma unroll
                for (int q = 0; q < 4; ++q) c[i][j][q] = 0.f;

        {
            float4 rA[4], rB[4];
            load_f32_g2(rA, ha, NF, va, tid);
            load_f32_g2(rB, w2e + (size_t)kb * NH, NH, 64, tid);
            store_split_g2(rA, sm, sm + 8192, tid);
            store_split_g2(rB, sm + 16384, sm + 24576, tid);
        }

        for (int kt = 0; kt < 16; ++kt) {
            __syncthreads();
            char* bb = sm + (kt & 1) * BSZ2;
            char* nb = sm + ((kt + 1) & 1) * BSZ2;
            const bool pf = (kt + 1) < 16;
            float4 rA[4], rB[4];
            if (pf) {
                const int k0 = (kt + 1) * 64;
                load_f32_g2(rA, ha + k0, NF, va, tid);
                load_f32_g2(rB, w2e + (size_t)(kb + k0) * NH, NH, 64, tid);
            }
            const uint32_t uAh = smem_u32(bb), uAl = uAh + 8192;
            const uint32_t uBh = uAh + 16384, uBl = uAh + 24576;
            #pragma unroll
            for (int kk = 0; kk < 4; ++kk) {
                uint32_t ah[2][4], al[2][4];
                #pragma unroll
                for (int mi = 0; mi < 2; ++mi) {
                    const uint32_t off =
                        sw128((uint32_t)((wm * 32 + mi * 16 + arow) * 128 + kk * 32 + acol));
                    ldm_x4(ah[mi], uAh + off);
                    ldm_x4(al[mi], uAl + off);
                }
                uint32_t bh[4], bl[4];
                {
                    const uint32_t off =
                        sw128((uint32_t)((kk * 16 + tbrow) * 128 + wn * 32 + tbcol));
                    ldm_x4_t(bh, uBh + off);
                    ldm_x4_t(bl, uBl + off);
                }
                #pragma unroll
                for (int mi = 0; mi < 2; ++mi)
                    #pragma unroll
                    for (int j = 0; j < 2; ++j) {
                        float* cc = c[mi][j];
                        mma_bf16(cc, ah[mi], &bh[j * 2]);
                        mma_bf16(cc, ah[mi], &bl[j * 2]);
                        mma_bf16(cc, al[mi], &bh[j * 2]);
                    }
            }
            if (pf) {
                store_split_g2(rA, nb, nb + 8192, tid);
                store_split_g2(rB, nb + 16384, nb + 24576, tid);
            }
        }

        // epilogue: atomic accumulate (exactly 2 contributions per element)
        const int r0 = lane >> 2, cp = (lane & 3) * 2;
        #pragma unroll
        for (int mi = 0; mi < 2; ++mi)
            #pragma unroll
            for (int nj = 0; nj < 2; ++nj) {
                const int rloc = wm * 32 + mi * 16 + r0;
                const int ncol = n0 + wn * 16 + nj * 8 + cp;
                if (rloc < va) {
                    float* p = &out[(size_t)(base + mm + rloc) * NH + ncol];
                    atomicAdd(p, c[mi][nj][0]);
                    atomicAdd(p + 1, c[mi][nj][1]);
                }
                if (rloc + 8 < va) {
                    float* p = &out[(size_t)(base + mm + rloc + 8) * NH + ncol];
                    atomicAdd(p, c[mi][nj][2]);
                    atomicAdd(p + 1, c[mi][nj][3]);
                }
            }
        __syncthreads();
    }
}

// ---------------------------------------------------------------------------
extern "C" void kernel_launch(void* const* d_in, const int* in_sizes, int n_in,
                              void* d_out, int out_size) {
    const float* x  = (const float*)d_in[0];
    const float* w1 = (const float*)d_in[1];
    const float* w2 = (const float*)d_in[2];
    const int* tokens_per_expert = (const int*)d_in[3];
    float* out = (float*)d_out;

    cudaFuncSetAttribute(gemm1_tc, cudaFuncAttributeMaxDynamicSharedMemorySize, 2 * BSZ1);
    cudaFuncSetAttribute(gemm2_tc, cudaFuncAttributeMaxDynamicSharedMemorySize, 2 * BSZ2);

    gemm1_tc<<<dim3(NF / 128, NE), 128, 2 * BSZ1>>>(x, w1, tokens_per_expert);
    zero_out<<<(NT * NH) / 1024, 256>>>((float4*)out);
    gemm2_tc<<<dim3(NH / 64, NE, 2), 256, 2 * BSZ2>>>(w2, out, tokens_per_expert);
}

// round 17
// speedup vs baseline: 1.0749x; 1.0176x over previous
#include <cuda_runtime.h>
#include <math.h>
#include <stdint.h>

#define NE 64
#define NH 512
#define NF 2048
#define NT 2048

// scratch: h = gelu(x @ w1^T) (16 MB)
__device__ float g_h[(size_t)NT * NF];

// ---------------- helpers ----------------
__device__ __forceinline__ uint32_t smem_u32(const void* p) {
    return (uint32_t)__cvta_generic_to_shared(p);
}
__device__ __forceinline__ uint32_t sw128(uint32_t off) { return off ^ ((off >> 3) & 0x70); }

__device__ __forceinline__ void ldm_x4(uint32_t* r, uint32_t a) {
    asm volatile("ldmatrix.sync.aligned.m8n8.x4.shared.b16 {%0,%1,%2,%3}, [%4];"
                 : "=r"(r[0]), "=r"(r[1]), "=r"(r[2]), "=r"(r[3]) : "r"(a));
}
__device__ __forceinline__ void ldm_x4_t(uint32_t* r, uint32_t a) {
    asm volatile("ldmatrix.sync.aligned.m8n8.x4.trans.shared.b16 {%0,%1,%2,%3}, [%4];"
                 : "=r"(r[0]), "=r"(r[1]), "=r"(r[2]), "=r"(r[3]) : "r"(a));
}
__device__ __forceinline__ void mma_bf16(float* c, const uint32_t* a, const uint32_t* b) {
    asm volatile(
        "mma.sync.aligned.m16n8k16.row.col.f32.bf16.bf16.f32 "
        "{%0,%1,%2,%3}, {%4,%5,%6,%7}, {%8,%9}, {%0,%1,%2,%3};"
        : "+f"(c[0]), "+f"(c[1]), "+f"(c[2]), "+f"(c[3])
        : "r"(a[0]), "r"(a[1]), "r"(a[2]), "r"(a[3]), "r"(b[0]), "r"(b[1]));
}
__device__ __forceinline__ float gelu_exact(float v) {
    return 0.5f * v * (1.0f + erff(v * 0.7071067811865476f));
}
__device__ __forceinline__ void split4(const float4 t, uint64_t& hi, uint64_t& lo) {
    uint32_t h01, h23, l01, l23;
    asm("cvt.rn.bf16x2.f32 %0, %1, %2;" : "=r"(h01) : "f"(t.y), "f"(t.x));
    asm("cvt.rn.bf16x2.f32 %0, %1, %2;" : "=r"(h23) : "f"(t.w), "f"(t.z));
    const float rx = t.x - __uint_as_float(h01 << 16);
    const float ry = t.y - __uint_as_float(h01 & 0xffff0000u);
    const float rz = t.z - __uint_as_float(h23 << 16);
    const float rw = t.w - __uint_as_float(h23 & 0xffff0000u);
    asm("cvt.rn.bf16x2.f32 %0, %1, %2;" : "=r"(l01) : "f"(ry), "f"(rx));
    asm("cvt.rn.bf16x2.f32 %0, %1, %2;" : "=r"(l23) : "f"(rw), "f"(rz));
    hi = ((uint64_t)h23 << 32) | h01;
    lo = ((uint64_t)l23 << 32) | l01;
}

__device__ __forceinline__ void expert_range(const int* __restrict__ counts, int e,
                                             int& base, int& cnt) {
    int b = 0, c = 0;
    #pragma unroll
    for (int j = 0; j < NE; ++j) {
        const int v = __ldg(counts + j);
        if (j < e) b += v;
        if (j == e) c = v;
    }
    base = b; cnt = c;
}

// ======== 128-thread tile helpers (gemm1, R14-proven) ========
// Tile: R rows x 64 f32 cols. 128 threads: 16 threads/row (float4), 8 rows/pass.
template<int R>
__device__ __forceinline__ void load_f32_g1(float4* v, const float* __restrict__ src,
                                            int stride, int valid, int tid) {
    const int row0 = tid >> 4, c4 = (tid & 15) * 4;
    #pragma unroll
    for (int p = 0; p < R / 8; ++p) {
        const int row = p * 8 + row0;
        v[p] = (row < valid) ? *(const float4*)(src + (size_t)row * stride + c4)
                             : make_float4(0.f, 0.f, 0.f, 0.f);
    }
}
template<int R>
__device__ __forceinline__ void store_split_g1(const float4* v, char* hi, char* lo, int tid) {
    const int row0 = tid >> 4, l15 = tid & 15;
    #pragma unroll
    for (int p = 0; p < R / 8; ++p) {
        const int row = p * 8 + row0;
        uint64_t h, l;
        split4(v[p], h, l);
        const uint32_t off = sw128((uint32_t)(row * 128 + l15 * 8));
        *(uint64_t*)(hi + off) = h;
        *(uint64_t*)(lo + off) = l;
    }
}

// ======== 256-thread tile helpers (gemm2, R8-proven) ========
// Tile: 64 rows x 64 f32 cols. 256 threads: 16 threads/row (float4), 16 rows/pass.
__device__ __forceinline__ void load_f32_g2(float4* v, const float* __restrict__ src,
                                            int stride, int valid, int tid) {
    const int row0 = tid >> 4, c4 = (tid & 15) * 4;
    #pragma unroll
    for (int p = 0; p < 4; ++p) {
        const int row = p * 16 + row0;
        v[p] = (row < valid) ? *(const float4*)(src + (size_t)row * stride + c4)
                             : make_float4(0.f, 0.f, 0.f, 0.f);
    }
}
__device__ __forceinline__ void store_split_g2(const float4* v, char* hi, char* lo, int tid) {
    const int row0 = tid >> 4, l15 = tid & 15;
    #pragma unroll
    for (int p = 0; p < 4; ++p) {
        const int row = p * 16 + row0;
        uint64_t h, l;
        split4(v[p], h, l);
        const uint32_t off = sw128((uint32_t)(row * 128 + l15 * 8));
        *(uint64_t*)(hi + off) = h;
        *(uint64_t*)(lo + off) = l;
    }
}

// gemm1 stage: [Ahi 4K][Alo 4K][Bhi 16K][Blo 16K] = 40K; x2 = 80K per CTA
#define BSZ1 (40 * 1024)
// gemm2 stage: [Ahi 8K][Alo 8K][Bhi 8K][Blo 8K] = 32K; x2 = 64K per CTA
#define BSZ2 (32 * 1024)

// ---------------- GEMM1 + GELU: h = gelu(x @ w1[e]^T) ------------------------
// CTA: (f-slab 128, expert). M=32, K-tiles of 64 (8). 4 warps = 1m x 4n.
// Warp tile 32m x 32n. (R14/R16 verbatim) + folded out-zeroing (R12-proven).
__global__ void __launch_bounds__(128, 2) gemm1_tc(const float* __restrict__ x,
                                                   const float* __restrict__ w1,
                                                   float* __restrict__ out,
                                                   const int* __restrict__ counts) {
    extern __shared__ char sm[];
    const int e  = blockIdx.y;
    const int sx = blockIdx.x;          // 0..15
    const int f0 = sx * 128;
    int base, cnt;
    expert_range(counts, e, base, cnt);
    const int tid = threadIdx.x, warp = tid >> 5, lane = tid & 31;
    const int wn = warp;   // 0..3
    const float* w1e = w1 + (size_t)e * NF * NH + (size_t)f0 * NH;

    // folded zero_out: 16 CTAs/expert x 128 threads cooperatively zero
    // this expert's out rows (cnt * 512 floats = cnt * 128 float4s).
    {
        float4* ob = (float4*)(out + (size_t)base * NH);
        const int tot = cnt * 128;
        for (int i = sx * 128 + tid; i < tot; i += 16 * 128)
            ob[i] = make_float4(0.f, 0.f, 0.f, 0.f);
    }

    const int arow = lane & 15, acol = lane & 16;        // A (plain)
    const int brow = (lane & 7) + ((lane >> 1) & 8);     // B (plain, [n][k])
    const int bcol = (lane & 8) * 2;

    for (int mm = 0; mm < cnt; mm += 32) {
        const int rem = cnt - mm;
        const int va = rem < 32 ? rem : 32;
        const float* xa = x + (size_t)(base + mm) * NH;

        float c[2][4][4];
        #pragma unroll
        for (int i = 0; i < 2; ++i)
            #pragma unroll
            for (int j = 0; j < 4; ++j)
                #pragma unroll
                for (int q = 0; q < 4; ++q) c[i][j][q] = 0.f;

        {
            float4 rA[4], rB[16];
            load_f32_g1<32>(rA, xa, NH, va, tid);
            load_f32_g1<128>(rB, w1e, NH, 128, tid);
            store_split_g1<32>(rA, sm, sm + 4096, tid);
            store_split_g1<128>(rB, sm + 8192, sm + 24576, tid);
        }

        for (int kt = 0; kt < 8; ++kt) {
            __syncthreads();
            char* bb = sm + (kt & 1) * BSZ1;
            char* nb = sm + ((kt + 1) & 1) * BSZ1;
            const bool pf = (kt + 1) < 8;
            float4 rA[4], rB[16];
            if (pf) {
                const int k0 = (kt + 1) * 64;
                load_f32_g1<32>(rA, xa + k0, NH, va, tid);
                load_f32_g1<128>(rB, w1e + k0, NH, 128, tid);
            }
            const uint32_t uAh = smem_u32(bb), uAl = uAh + 4096;
            const uint32_t uBh = uAh + 8192, uBl = uAh + 24576;
            #pragma unroll
            for (int kk = 0; kk < 4; ++kk) {
                uint32_t ah[2][4], al[2][4];
                #pragma unroll
                for (int mi = 0; mi < 2; ++mi) {
                    const uint32_t off =
                        sw128((uint32_t)((mi * 16 + arow) * 128 + kk * 32 + acol));
                    ldm_x4(ah[mi], uAh + off);
                    ldm_x4(al[mi], uAl + off);
                }
                #pragma unroll
                for (int nbk = 0; nbk < 2; ++nbk) {
                    uint32_t bh[4], bl[4];
                    const uint32_t off =
                        sw128((uint32_t)((wn * 32 + nbk * 16 + brow) * 128 + kk * 32 + bcol));
                    ldm_x4(bh, uBh + off);
                    ldm_x4(bl, uBl + off);
                    #pragma unroll
                    for (int mi = 0; mi < 2; ++mi)
                        #pragma unroll
                        for (int j = 0; j < 2; ++j) {
                            float* cc = c[mi][nbk * 2 + j];
                            mma_bf16(cc, ah[mi], &bh[j * 2]);
                            mma_bf16(cc, ah[mi], &bl[j * 2]);
                            mma_bf16(cc, al[mi], &bh[j * 2]);
                        }
                }
            }
            if (pf) {
                store_split_g1<32>(rA, nb, nb + 4096, tid);
                store_split_g1<128>(rB, nb + 8192, nb + 24576, tid);
            }
        }

        const int r0 = lane >> 2, cp = (lane & 3) * 2;
        #pragma unroll
        for (int mi = 0; mi < 2; ++mi)
            #pragma unroll
            for (int nj = 0; nj < 4; ++nj) {
                const int rloc = mi * 16 + r0;
                const int ncol = f0 + wn * 32 + (nj >> 1) * 16 + (nj & 1) * 8 + cp;
                if (rloc < va) {
                    float2 o = make_float2(gelu_exact(c[mi][nj][0]), gelu_exact(c[mi][nj][1]));
                    *(float2*)&g_h[(size_t)(base + mm + rloc) * NF + ncol] = o;
                }
                if (rloc + 8 < va) {
                    float2 o = make_float2(gelu_exact(c[mi][nj][2]), gelu_exact(c[mi][nj][3]));
                    *(float2*)&g_h[(size_t)(base + mm + rloc + 8) * NF + ncol] = o;
                }
            }
        __syncthreads();
    }
}

// ---------------- GEMM2: out += h @ w2[e]  (k-split x2, atomic epilogue) -----
// CTA: (n-slab 64, expert, k-half). M=64 padded, K-tiles of 64 (16 per half).
// 256 threads, 8 warps = 2m x 4n. (R8/R16 verbatim — measured ~93.5us)
__global__ void __launch_bounds__(256, 2) gemm2_tc(const float* __restrict__ w2,
                                                   float* __restrict__ out,
                                                   const int* __restrict__ counts) {
    extern __shared__ char sm[];
    const int e  = blockIdx.y;
    const int n0 = blockIdx.x * 64;
    const int kb = blockIdx.z * 1024;
    int base, cnt;
    expert_range(counts, e, base, cnt);
    const int tid = threadIdx.x, warp = tid >> 5, lane = tid & 31;
    const int wm = warp >> 2, wn = warp & 3;
    const float* w2e = w2 + (size_t)e * NF * NH + n0;

    const int arow = lane & 15, acol = lane & 16;   // A (plain)
    const int tbrow = lane & 15, tbcol = lane & 16; // B (trans, [k][n])

    for (int mm = 0; mm < cnt; mm += 64) {
        const int rem = cnt - mm;
        const int va = rem < 64 ? rem : 64;
        const float* ha = g_h + (size_t)(base + mm) * NF + kb;

        float c[2][2][4];
        #pragma unroll
        for (int i = 0; i < 2; ++i)
            #pragma unroll
            for (int j = 0; j < 2; ++j)
                #pragma unroll
                for (int q = 0; q < 4; ++q) c[i][j][q] = 0.f;

        {
            float4 rA[4], rB[4];
            load_f32_g2(rA, ha, NF, va, tid);
            load_f32_g2(rB, w2e + (size_t)kb * NH, NH, 64, tid);
            store_split_g2(rA, sm, sm + 8192, tid);
            store_split_g2(rB, sm + 16384, sm + 24576, tid);
        }

        for (int kt = 0; kt < 16; ++kt) {
            __syncthreads();
            char* bb = sm + (kt & 1) * BSZ2;
            char* nb = sm + ((kt + 1) & 1) * BSZ2;
            const bool pf = (kt + 1) < 16;
            float4 rA[4], rB[4];
            if (pf) {
                const int k0 = (kt + 1) * 64;
                load_f32_g2(rA, ha + k0, NF, va, tid);
                load_f32_g2(rB, w2e + (size_t)(kb + k0) * NH, NH, 64, tid);
            }
            const uint32_t uAh = smem_u32(bb), uAl = uAh + 8192;
            const uint32_t uBh = uAh + 16384, uBl = uAh + 24576;
            #pragma unroll
            for (int kk = 0; kk < 4; ++kk) {
                uint32_t ah[2][4], al[2][4];
                #pragma unroll
                for (int mi = 0; mi < 2; ++mi) {
                    const uint32_t off =
                        sw128((uint32_t)((wm * 32 + mi * 16 + arow) * 128 + kk * 32 + acol));
                    ldm_x4(ah[mi], uAh + off);
                    ldm_x4(al[mi], uAl + off);
                }
                uint32_t bh[4], bl[4];
                {
                    const uint32_t off =
                        sw128((uint32_t)((kk * 16 + tbrow) * 128 + wn * 32 + tbcol));
                    ldm_x4_t(bh, uBh + off);
                    ldm_x4_t(bl, uBl + off);
                }
                #pragma unroll
                for (int mi = 0; mi < 2; ++mi)
                    #pragma unroll
                    for (int j = 0; j < 2; ++j) {
                        float* cc = c[mi][j];
                        mma_bf16(cc, ah[mi], &bh[j * 2]);
                        mma_bf16(cc, ah[mi], &bl[j * 2]);
                        mma_bf16(cc, al[mi], &bh[j * 2]);
                    }
            }
            if (pf) {
                store_split_g2(rA, nb, nb + 8192, tid);
                store_split_g2(rB, nb + 16384, nb + 24576, tid);
            }
        }

        // epilogue: atomic accumulate (exactly 2 contributions per element)
        const int r0 = lane >> 2, cp = (lane & 3) * 2;
        #pragma unroll
        for (int mi = 0; mi < 2; ++mi)
            #pragma unroll
            for (int nj = 0; nj < 2; ++nj) {
                const int rloc = wm * 32 + mi * 16 + r0;
                const int ncol = n0 + wn * 16 + nj * 8 + cp;
                if (rloc < va) {
                    float* p = &out[(size_t)(base + mm + rloc) * NH + ncol];
                    atomicAdd(p, c[mi][nj][0]);
                    atomicAdd(p + 1, c[mi][nj][1]);
                }
                if (rloc + 8 < va) {
                    float* p = &out[(size_t)(base + mm + rloc + 8) * NH + ncol];
                    atomicAdd(p, c[mi][nj][2]);
                    atomicAdd(p + 1, c[mi][nj][3]);
                }
            }
        __syncthreads();
    }
}

// ---------------------------------------------------------------------------
extern "C" void kernel_launch(void* const* d_in, const int* in_sizes, int n_in,
                              void* d_out, int out_size) {
    const float* x  = (const float*)d_in[0];
    const float* w1 = (const float*)d_in[1];
    const float* w2 = (const float*)d_in[2];
    const int* tokens_per_expert = (const int*)d_in[3];
    float* out = (float*)d_out;

    cudaFuncSetAttribute(gemm1_tc, cudaFuncAttributeMaxDynamicSharedMemorySize, 2 * BSZ1);
    cudaFuncSetAttribute(gemm2_tc, cudaFuncAttributeMaxDynamicSharedMemorySize, 2 * BSZ2);

    gemm1_tc<<<dim3(NF / 128, NE), 128, 2 * BSZ1>>>(x, w1, out, tokens_per_expert);
    gemm2_tc<<<dim3(NH / 64, NE, 2), 256, 2 * BSZ2>>>(w2, out, tokens_per_expert);
}